// round 1
// baseline (speedup 1.0000x reference)
#include <cuda_runtime.h>
#include <cuda_fp16.h>
#include <cstdint>

// ---------------- problem constants ----------------
#define T_STEPS 4096
#define H_DIM   2048
#define IN_DIM  2048
#define G3      6144          // 3 * H_DIM

// ---------------- scan configuration ----------------
#define GRID_SCAN    128      // persistent CTAs (<= 148 SMs, 1 CTA/SM)
#define CHUNK        16       // hidden indices per CTA (128*16 = 2048)
#define ROWS         48       // 3 gates * CHUNK rows of Wh per CTA
#define THREADS_SCAN 384      // ROWS * 8 column-groups

// scratch: igates buffer + per-step barrier counters
__device__ float        g_igates[(size_t)T_STEPS * G3];
__device__ unsigned int g_arrive[T_STEPS];

__device__ __forceinline__ float sigmoidf_(float x) {
    return 1.0f / (1.0f + __expf(-x));
}

// =====================================================================
// Kernel 1: igates = xs @ Wi^T + bi      (fp32 SIMT tiled GEMM)
//   A = xs   [4096][2048]  row-major (K contiguous)
//   B = Wi   [6144][2048]  row-major (K contiguous)  -> "NT" gemm
//   C = g_igates [4096][6144]
// Tile 128x128x16, 256 threads, 8x8 per thread, register prefetch.
// Also zeroes the scan barrier array.
// =====================================================================
__global__ void __launch_bounds__(256, 2)
igates_gemm(const float* __restrict__ A,
            const float* __restrict__ B,
            const float* __restrict__ bias)
{
    __shared__ float As[16][128];
    __shared__ float Bs[16][128];

    const int tid = threadIdx.x;
    const int bm  = blockIdx.y * 128;
    const int bn  = blockIdx.x * 128;

    // zero the scan barrier counters (grid is 1536 CTAs -> plenty)
    {
        int g = (blockIdx.y * gridDim.x + blockIdx.x) * 256 + tid;
        if (g < T_STEPS) g_arrive[g] = 0;
    }

    // ---- global->reg staging mapping: each thread loads 8 consecutive
    //      floats (2 float4) of one row per tile, per matrix.
    const int r  = tid >> 1;          // 0..127  tile row
    const int h8 = (tid & 1) * 8;     // 0 or 8  k offset
    const float* Ap = A + (size_t)(bm + r) * IN_DIM + h8;
    const float* Bp = B + (size_t)(bn + r) * IN_DIM + h8;

    float4 ra0 = *(const float4*)(Ap);
    float4 ra1 = *(const float4*)(Ap + 4);
    float4 rb0 = *(const float4*)(Bp);
    float4 rb1 = *(const float4*)(Bp + 4);

    const int tx = tid & 15;          // 0..15 -> cols tx*4, 64+tx*4
    const int ty = tid >> 4;          // 0..15 -> rows ty*4, 64+ty*4

    float acc[8][8];
    #pragma unroll
    for (int i = 0; i < 8; i++)
        #pragma unroll
        for (int j = 0; j < 8; j++)
            acc[i][j] = 0.0f;

    const int NKT = IN_DIM / 16;      // 128 k-tiles
    for (int kt = 0; kt < NKT; kt++) {
        // staged regs -> smem (transposed: [k][row])
        As[h8 + 0][r] = ra0.x; As[h8 + 1][r] = ra0.y;
        As[h8 + 2][r] = ra0.z; As[h8 + 3][r] = ra0.w;
        As[h8 + 4][r] = ra1.x; As[h8 + 5][r] = ra1.y;
        As[h8 + 6][r] = ra1.z; As[h8 + 7][r] = ra1.w;
        Bs[h8 + 0][r] = rb0.x; Bs[h8 + 1][r] = rb0.y;
        Bs[h8 + 2][r] = rb0.z; Bs[h8 + 3][r] = rb0.w;
        Bs[h8 + 4][r] = rb1.x; Bs[h8 + 5][r] = rb1.y;
        Bs[h8 + 6][r] = rb1.z; Bs[h8 + 7][r] = rb1.w;
        __syncthreads();

        if (kt + 1 < NKT) {           // prefetch next tile into regs
            const float* An = Ap + (kt + 1) * 16;
            const float* Bn = Bp + (kt + 1) * 16;
            ra0 = *(const float4*)(An);
            ra1 = *(const float4*)(An + 4);
            rb0 = *(const float4*)(Bn);
            rb1 = *(const float4*)(Bn + 4);
        }

        #pragma unroll
        for (int k = 0; k < 16; k++) {
            const float4 a0 = *(const float4*)&As[k][ty * 4];
            const float4 a1 = *(const float4*)&As[k][64 + ty * 4];
            const float4 b0 = *(const float4*)&Bs[k][tx * 4];
            const float4 b1 = *(const float4*)&Bs[k][64 + tx * 4];
            float am[8] = {a0.x, a0.y, a0.z, a0.w, a1.x, a1.y, a1.z, a1.w};
            float bb[8] = {b0.x, b0.y, b0.z, b0.w, b1.x, b1.y, b1.z, b1.w};
            #pragma unroll
            for (int i = 0; i < 8; i++)
                #pragma unroll
                for (int j = 0; j < 8; j++)
                    acc[i][j] = fmaf(am[i], bb[j], acc[i][j]);
        }
        __syncthreads();
    }

    // epilogue: + bias, store fp32
    const float4 bi0 = *(const float4*)&bias[bn + tx * 4];
    const float4 bi1 = *(const float4*)&bias[bn + 64 + tx * 4];
    #pragma unroll
    for (int i = 0; i < 8; i++) {
        const int m = bm + ((i < 4) ? (ty * 4 + i) : (64 + ty * 4 + (i - 4)));
        float* Crow = g_igates + (size_t)m * G3 + bn;
        float4 v0, v1;
        v0.x = acc[i][0] + bi0.x; v0.y = acc[i][1] + bi0.y;
        v0.z = acc[i][2] + bi0.z; v0.w = acc[i][3] + bi0.w;
        v1.x = acc[i][4] + bi1.x; v1.y = acc[i][5] + bi1.y;
        v1.z = acc[i][6] + bi1.z; v1.w = acc[i][7] + bi1.w;
        *(float4*)(Crow + tx * 4)      = v0;
        *(float4*)(Crow + 64 + tx * 4) = v1;
    }
}

// =====================================================================
// Kernel 2: persistent GRU scan.
// 128 CTAs; CTA b owns hidden indices j in [16b, 16b+16). It holds the
// 48 corresponding Wh rows (r,z,n for those j) as fp16 in SMEM (196 KB).
// Per step: matvec slices -> gate math for its 16 j -> write out[t] ->
// one grid-wide release/acquire barrier -> next step reads out[t] (L2).
//
// Thread layout: tid = row*8 + cg  (row 0..47, cg 0..7).
// Weight SMEM layout (uint4 = 8 fp16 = 8 columns for (i,row,cg)):
//   wq[i*384 + row*8 + cg]   covers columns i*64 + cg*8 + [0..8)
// so each warp's LDS.128 hits 512 contiguous bytes (conflict-free), and
// the h reads per warp are 8 distinct float4s + broadcast (coalesced).
// =====================================================================
__global__ void __launch_bounds__(THREADS_SCAN, 1)
gru_scan(const float* __restrict__ init_state,
         const float* __restrict__ Wh,
         const float* __restrict__ bn_vec,
         float* __restrict__ out,
         int out_size)
{
    extern __shared__ __half2 wbuf[];            // 49152 half2 = 196608 B
    __shared__ float dots[ROWS];

    const int tid   = threadIdx.x;
    const int jbase = blockIdx.x * CHUNK;

    // ---- load + convert Wh slice (fp32 -> fp16), once per launch ----
    for (int idx = tid; idx < 32 * ROWS * 8 * 4; idx += THREADS_SCAN) {
        const int e4  = idx & 3;
        const int cg  = (idx >> 2) & 7;
        const int ir  = idx >> 5;                // i*ROWS + row
        const int row = ir % ROWS;
        const int i   = ir / ROWS;
        const int col = i * 64 + cg * 8 + e4 * 2;
        const int grow = (row >> 4) * H_DIM + jbase + (row & 15);
        const float2 w2 = *(const float2*)(Wh + (size_t)grow * H_DIM + col);
        wbuf[idx] = __floats2half2_rn(w2.x, w2.y);
    }

    const int row = tid >> 3;                    // 0..47
    const int cg  = tid & 7;                     // 0..7
    const float bnj = (tid < CHUNK) ? bn_vec[jbase + tid] : 0.0f;
    const uint4* wq = (const uint4*)wbuf;

    __syncthreads();

    for (int t = 0; t < T_STEPS; t++) {
        const float* hsrc = (t == 0) ? init_state
                                     : (out + (size_t)(t - 1) * H_DIM);
        const float4* h4 = (const float4*)hsrc;

        // prefetch igates + previous h for the gate phase (latency hidden
        // behind the matvec below)
        float igr = 0.f, igz = 0.f, ign = 0.f, hprev = 0.f;
        if (tid < CHUNK) {
            const float* igb = g_igates + (size_t)t * G3 + jbase + tid;
            igr   = __ldg(igb);
            igz   = __ldg(igb + H_DIM);
            ign   = __ldg(igb + 2 * H_DIM);
            hprev = __ldg(hsrc + jbase + tid);
        }

        // ---- matvec: this thread accumulates row `row` over its 256 cols
        float acc = 0.0f;
        const int hoff = cg * 2;
        #pragma unroll 8
        for (int i = 0; i < 32; i++) {
            const uint4  w  = wq[i * (ROWS * 8) + tid];
            const float4 ha = __ldg(h4 + i * 16 + hoff);
            const float4 hb = __ldg(h4 + i * 16 + hoff + 1);
            float2 f;
            f = __half22float2(*(const __half2*)&w.x);
            acc = fmaf(f.x, ha.x, acc); acc = fmaf(f.y, ha.y, acc);
            f = __half22float2(*(const __half2*)&w.y);
            acc = fmaf(f.x, ha.z, acc); acc = fmaf(f.y, ha.w, acc);
            f = __half22float2(*(const __half2*)&w.z);
            acc = fmaf(f.x, hb.x, acc); acc = fmaf(f.y, hb.y, acc);
            f = __half22float2(*(const __half2*)&w.w);
            acc = fmaf(f.x, hb.z, acc); acc = fmaf(f.y, hb.w, acc);
        }
        // reduce across the 8 column-groups (lanes cg 0..7 of the row)
        acc += __shfl_xor_sync(0xffffffffu, acc, 1);
        acc += __shfl_xor_sync(0xffffffffu, acc, 2);
        acc += __shfl_xor_sync(0xffffffffu, acc, 4);
        if (cg == 0) dots[row] = acc;
        __syncthreads();

        // ---- gate math for this CTA's 16 hidden indices
        if (tid < CHUNK) {
            const float hr = dots[tid];
            const float hz = dots[CHUNK + tid];
            const float hn = dots[2 * CHUNK + tid];
            const float reset = sigmoidf_(igr + hr);
            const float upd   = sigmoidf_(igz + hz);
            const float cand  = tanhf(ign + reset * (hn + bnj));
            const float hnew  = (1.0f - upd) * cand + upd * hprev;
            out[(size_t)t * H_DIM + jbase + tid] = hnew;
            if (t == T_STEPS - 1) {
                const int tail = T_STEPS * H_DIM + jbase + tid;
                if (tail < out_size) out[tail] = hnew;   // last_state
            }
        }

        // ---- grid-wide barrier (release writes, acquire reads)
        __threadfence();
        __syncthreads();
        if (tid == 0) {
            unsigned int* flag = &g_arrive[t];
            asm volatile("red.release.gpu.add.u32 [%0], 1;"
                         :: "l"(flag) : "memory");
            unsigned int v;
            do {
                asm volatile("ld.acquire.gpu.u32 %0, [%1];"
                             : "=r"(v) : "l"(flag) : "memory");
            } while (v < GRID_SCAN);
        }
        __syncthreads();
    }
}

// =====================================================================
// launch
// =====================================================================
extern "C" void kernel_launch(void* const* d_in, const int* in_sizes, int n_in,
                              void* d_out, int out_size)
{
    const float* xs         = (const float*)d_in[0];
    const float* init_state = (const float*)d_in[1];
    const float* Wi         = (const float*)d_in[2];
    const float* Wh         = (const float*)d_in[3];
    const float* bi         = (const float*)d_in[4];
    const float* bn         = (const float*)d_in[5];
    float* out = (float*)d_out;
    (void)in_sizes; (void)n_in;

    // 1) igates GEMM (also zeroes barrier counters)
    dim3 ggrid(G3 / 128, T_STEPS / 128);   // (48, 32)
    igates_gemm<<<ggrid, 256>>>(xs, Wi, bi);

    // 2) persistent scan
    const int smem_bytes = 32 * ROWS * 8 * 4 * (int)sizeof(__half2); // 196608
    cudaFuncSetAttribute(gru_scan,
                         cudaFuncAttributeMaxDynamicSharedMemorySize,
                         smem_bytes);
    gru_scan<<<GRID_SCAN, THREADS_SCAN, smem_bytes>>>(init_state, Wh, bn,
                                                      out, out_size);
}

// round 4
// speedup vs baseline: 1.0035x; 1.0035x over previous
#include <cuda_runtime.h>
#include <cuda_fp16.h>
#include <cstdint>

// ---------------- problem constants ----------------
#define T_STEPS 4096
#define H_DIM   2048
#define IN_DIM  2048
#define G3      6144          // 3 * H_DIM

// ---------------- scan configuration ----------------
#define GRID_SCAN    128      // persistent CTAs (<= 148 SMs, 1 CTA/SM)
#define CHUNK        16       // hidden indices per CTA (128*16 = 2048)
#define ROWS         48       // 3 gates * CHUNK rows of Wh per CTA
#define THREADS_SCAN 384      // ROWS * 8 column-groups

#define WBUF_BYTES   (32 * ROWS * 8 * 4 * 4)   // 196608 B of fp16 weights
#define HBUF_BYTES   (H_DIM * 4)               // 8192 B staged h
#define SMEM_SCAN    (WBUF_BYTES + HBUF_BYTES) // 204800 B

// scratch: igates buffer + per-step barrier counters
__device__ float        g_igates[(size_t)T_STEPS * G3];
__device__ unsigned int g_arrive[T_STEPS];

__device__ __forceinline__ float sigmoidf_(float x) {
    return 1.0f / (1.0f + __expf(-x));
}

// =====================================================================
// Kernel 1: igates = xs @ Wi^T + bi      (fp32 SIMT tiled GEMM)
// Tile 128x128x16, 256 threads, 8x8 per thread, register prefetch.
// Also zeroes the scan barrier array.
// =====================================================================
__global__ void __launch_bounds__(256, 2)
igates_gemm(const float* __restrict__ A,
            const float* __restrict__ B,
            const float* __restrict__ bias)
{
    __shared__ float As[16][128];
    __shared__ float Bs[16][128];

    const int tid = threadIdx.x;
    const int bm  = blockIdx.y * 128;
    const int bn  = blockIdx.x * 128;

    {
        int g = (blockIdx.y * gridDim.x + blockIdx.x) * 256 + tid;
        if (g < T_STEPS) g_arrive[g] = 0;
    }

    const int r  = tid >> 1;          // 0..127  tile row
    const int h8 = (tid & 1) * 8;     // 0 or 8  k offset
    const float* Ap = A + (size_t)(bm + r) * IN_DIM + h8;
    const float* Bp = B + (size_t)(bn + r) * IN_DIM + h8;

    float4 ra0 = *(const float4*)(Ap);
    float4 ra1 = *(const float4*)(Ap + 4);
    float4 rb0 = *(const float4*)(Bp);
    float4 rb1 = *(const float4*)(Bp + 4);

    const int tx = tid & 15;
    const int ty = tid >> 4;

    float acc[8][8];
    #pragma unroll
    for (int i = 0; i < 8; i++)
        #pragma unroll
        for (int j = 0; j < 8; j++)
            acc[i][j] = 0.0f;

    const int NKT = IN_DIM / 16;
    for (int kt = 0; kt < NKT; kt++) {
        As[h8 + 0][r] = ra0.x; As[h8 + 1][r] = ra0.y;
        As[h8 + 2][r] = ra0.z; As[h8 + 3][r] = ra0.w;
        As[h8 + 4][r] = ra1.x; As[h8 + 5][r] = ra1.y;
        As[h8 + 6][r] = ra1.z; As[h8 + 7][r] = ra1.w;
        Bs[h8 + 0][r] = rb0.x; Bs[h8 + 1][r] = rb0.y;
        Bs[h8 + 2][r] = rb0.z; Bs[h8 + 3][r] = rb0.w;
        Bs[h8 + 4][r] = rb1.x; Bs[h8 + 5][r] = rb1.y;
        Bs[h8 + 6][r] = rb1.z; Bs[h8 + 7][r] = rb1.w;
        __syncthreads();

        if (kt + 1 < NKT) {
            const float* An = Ap + (kt + 1) * 16;
            const float* Bn = Bp + (kt + 1) * 16;
            ra0 = *(const float4*)(An);
            ra1 = *(const float4*)(An + 4);
            rb0 = *(const float4*)(Bn);
            rb1 = *(const float4*)(Bn + 4);
        }

        #pragma unroll
        for (int k = 0; k < 16; k++) {
            const float4 a0 = *(const float4*)&As[k][ty * 4];
            const float4 a1 = *(const float4*)&As[k][64 + ty * 4];
            const float4 b0 = *(const float4*)&Bs[k][tx * 4];
            const float4 b1 = *(const float4*)&Bs[k][64 + tx * 4];
            float am[8] = {a0.x, a0.y, a0.z, a0.w, a1.x, a1.y, a1.z, a1.w};
            float bb[8] = {b0.x, b0.y, b0.z, b0.w, b1.x, b1.y, b1.z, b1.w};
            #pragma unroll
            for (int i = 0; i < 8; i++)
                #pragma unroll
                for (int j = 0; j < 8; j++)
                    acc[i][j] = fmaf(am[i], bb[j], acc[i][j]);
        }
        __syncthreads();
    }

    const float4 bi0 = *(const float4*)&bias[bn + tx * 4];
    const float4 bi1 = *(const float4*)&bias[bn + 64 + tx * 4];
    #pragma unroll
    for (int i = 0; i < 8; i++) {
        const int m = bm + ((i < 4) ? (ty * 4 + i) : (64 + ty * 4 + (i - 4)));
        float* Crow = g_igates + (size_t)m * G3 + bn;
        float4 v0, v1;
        v0.x = acc[i][0] + bi0.x; v0.y = acc[i][1] + bi0.y;
        v0.z = acc[i][2] + bi0.z; v0.w = acc[i][3] + bi0.w;
        v1.x = acc[i][4] + bi1.x; v1.y = acc[i][5] + bi1.y;
        v1.z = acc[i][6] + bi1.z; v1.w = acc[i][7] + bi1.w;
        *(float4*)(Crow + tx * 4)      = v0;
        *(float4*)(Crow + 64 + tx * 4) = v1;
    }
}

// =====================================================================
// Kernel 2: persistent GRU scan (h staged in SMEM each step).
// 128 CTAs; CTA b owns hidden indices [16b, 16b+16): 48 Wh rows as fp16
// in SMEM (192 KB). Per step:
//   1) cooperatively stage full h (8 KB) global->SMEM  (512 LDG.128/CTA)
//   2) matvec entirely from SMEM (LDS weights + LDS h)
//   3) gate math for 16 indices, write out[t]
//   4) grid release/acquire barrier
// =====================================================================
__global__ void __launch_bounds__(THREADS_SCAN, 1)
gru_scan(const float* __restrict__ init_state,
         const float* __restrict__ Wh,
         const float* __restrict__ bn_vec,
         float* __restrict__ out,
         int out_size)
{
    extern __shared__ unsigned char smem_raw[];
    __half2* wbuf = (__half2*)smem_raw;                       // 196608 B
    float4*  hsm  = (float4*)(smem_raw + WBUF_BYTES);         // 8192 B
    __shared__ float dots[ROWS];

    const int tid   = threadIdx.x;
    const int jbase = blockIdx.x * CHUNK;

    // ---- load + convert Wh slice (fp32 -> fp16), once per launch ----
    for (int idx = tid; idx < 32 * ROWS * 8 * 4; idx += THREADS_SCAN) {
        const int e4  = idx & 3;
        const int cg  = (idx >> 2) & 7;
        const int ir  = idx >> 5;                // i*ROWS + row
        const int row = ir % ROWS;
        const int i   = ir / ROWS;
        const int col = i * 64 + cg * 8 + e4 * 2;
        const int grow = (row >> 4) * H_DIM + jbase + (row & 15);
        const float2 w2 = *(const float2*)(Wh + (size_t)grow * H_DIM + col);
        wbuf[idx] = __floats2half2_rn(w2.x, w2.y);
    }

    const int row = tid >> 3;                    // 0..47
    const int cg  = tid & 7;                     // 0..7
    const float bnj = (tid < CHUNK) ? bn_vec[jbase + tid] : 0.0f;
    const uint4* wq = (const uint4*)wbuf;
    const float* hsm_f = (const float*)hsm;

    __syncthreads();

    for (int t = 0; t < T_STEPS; t++) {
        // prefetch igates for this step (independent of h)
        float igr = 0.f, igz = 0.f, ign = 0.f;
        if (tid < CHUNK) {
            const float* igb = g_igates + (size_t)t * G3 + jbase + tid;
            igr = __ldg(igb);
            igz = __ldg(igb + H_DIM);
            ign = __ldg(igb + 2 * H_DIM);
        }

        // ---- stage h into SMEM (fresh addresses every step; L2 reads)
        const float4* hg = (t == 0) ? (const float4*)init_state
                                    : (const float4*)(out + (size_t)(t - 1) * H_DIM);
        #pragma unroll
        for (int idx = tid; idx < H_DIM / 4; idx += THREADS_SCAN)
            hsm[idx] = __ldg(hg + idx);
        __syncthreads();

        // ---- matvec: row `row`, 256 columns, all operands in SMEM
        float acc = 0.0f;
        const int hoff = cg * 2;
        #pragma unroll 8
        for (int i = 0; i < 32; i++) {
            const uint4  w  = wq[i * (ROWS * 8) + tid];
            const float4 ha = hsm[i * 16 + hoff];
            const float4 hb = hsm[i * 16 + hoff + 1];
            float2 f;
            f = __half22float2(*(const __half2*)&w.x);
            acc = fmaf(f.x, ha.x, acc); acc = fmaf(f.y, ha.y, acc);
            f = __half22float2(*(const __half2*)&w.y);
            acc = fmaf(f.x, ha.z, acc); acc = fmaf(f.y, ha.w, acc);
            f = __half22float2(*(const __half2*)&w.z);
            acc = fmaf(f.x, hb.x, acc); acc = fmaf(f.y, hb.y, acc);
            f = __half22float2(*(const __half2*)&w.w);
            acc = fmaf(f.x, hb.z, acc); acc = fmaf(f.y, hb.w, acc);
        }
        acc += __shfl_xor_sync(0xffffffffu, acc, 1);
        acc += __shfl_xor_sync(0xffffffffu, acc, 2);
        acc += __shfl_xor_sync(0xffffffffu, acc, 4);
        if (cg == 0) dots[row] = acc;
        __syncthreads();

        // ---- gate math for this CTA's 16 hidden indices
        if (tid < CHUNK) {
            const float hprev = hsm_f[jbase + tid];
            const float hr = dots[tid];
            const float hz = dots[CHUNK + tid];
            const float hn = dots[2 * CHUNK + tid];
            const float reset = sigmoidf_(igr + hr);
            const float upd   = sigmoidf_(igz + hz);
            const float cand  = tanhf(ign + reset * (hn + bnj));
            const float hnew  = (1.0f - upd) * cand + upd * hprev;
            out[(size_t)t * H_DIM + jbase + tid] = hnew;
            if (t == T_STEPS - 1) {
                const int tail = T_STEPS * H_DIM + jbase + tid;
                if (tail < out_size) out[tail] = hnew;   // last_state
            }
        }

        // ---- grid-wide barrier (release writes, acquire reads)
        __threadfence();
        __syncthreads();
        if (tid == 0) {
            unsigned int* flag = &g_arrive[t];
            asm volatile("red.release.gpu.add.u32 [%0], 1;"
                         :: "l"(flag) : "memory");
            unsigned int v;
            do {
                asm volatile("ld.acquire.gpu.u32 %0, [%1];"
                             : "=r"(v) : "l"(flag) : "memory");
            } while (v < GRID_SCAN);
        }
        __syncthreads();
    }
}

// =====================================================================
// launch
// =====================================================================
extern "C" void kernel_launch(void* const* d_in, const int* in_sizes, int n_in,
                              void* d_out, int out_size)
{
    const float* xs         = (const float*)d_in[0];
    const float* init_state = (const float*)d_in[1];
    const float* Wi         = (const float*)d_in[2];
    const float* Wh         = (const float*)d_in[3];
    const float* bi         = (const float*)d_in[4];
    const float* bn         = (const float*)d_in[5];
    float* out = (float*)d_out;
    (void)in_sizes; (void)n_in;

    // 1) igates GEMM (also zeroes barrier counters)
    dim3 ggrid(G3 / 128, T_STEPS / 128);   // (48, 32)
    igates_gemm<<<ggrid, 256>>>(xs, Wi, bi);

    // 2) persistent scan
    cudaFuncSetAttribute(gru_scan,
                         cudaFuncAttributeMaxDynamicSharedMemorySize,
                         SMEM_SCAN);
    gru_scan<<<GRID_SCAN, THREADS_SCAN, SMEM_SCAN>>>(init_state, Wh, bn,
                                                     out, out_size);
}